// round 4
// baseline (speedup 1.0000x reference)
#include <cuda_runtime.h>
#include <cstdint>

#define Nn      6144
#define Dd      256
#define KP      300
#define NT      17
#define NSLOT   (KP * NT)          // 5100
#define NCTA    136                // 17 types * 8 sub-slices
#define ROWCAP  64
#define ITERS   30
#define INVTAU  20.0f              // 1/0.05
#define DUMMY_MASS 1044.0f         // N - n_slots

#define DEV_NEG_INF (__int_as_float(0xff800000))

// ---------------- device scratch (no runtime allocation) ------------------
__device__ float    g_h[(size_t)Nn * Dd];
__device__ float    g_hnorm[Nn];
__device__ float    g_pnorm[512];
__device__ float    g_M[(size_t)Nn * KP];          // rows in sorted-by-type order
__device__ int      g_perm[Nn];                    // sorted idx -> original row
__device__ int      g_tstart[NT + 1];
__device__ float2   g_cpart[2][NT * KP * 8];       // [parity][(t*KP+j)*8+sub]
__device__ float2   g_upart[2][NCTA];
__device__ unsigned g_flag[NCTA];

// ---------------- warp reductions -----------------------------------------
__device__ __forceinline__ float wred_max(float m) {
#pragma unroll
    for (int o = 16; o; o >>= 1) m = fmaxf(m, __shfl_xor_sync(0xffffffffu, m, o));
    return m;
}
__device__ __forceinline__ float wred_sum(float s) {
#pragma unroll
    for (int o = 16; o; o >>= 1) s += __shfl_xor_sync(0xffffffffu, s, o);
    return s;
}

// ---------------- deterministic counting sort by joint type (1 CTA) -------
__global__ __launch_bounds__(256) void sort_kernel(const int* __restrict__ jt)
{
    __shared__ int hist[NT][256];
    __shared__ int scratch[256];
    __shared__ int tot[NT];
    __shared__ int tstart_s[NT + 1];
    int tid = threadIdx.x;
    if (tid < NCTA) g_flag[tid] = 0;   // reset grid-barrier flags every replay
#pragma unroll
    for (int t = 0; t < NT; ++t) hist[t][tid] = 0;
    __syncthreads();

    const int CH = Nn / 256;           // 24
    int s0 = tid * CH;
    for (int i = 0; i < CH; ++i) hist[jt[s0 + i]][tid]++;
    __syncthreads();

    for (int t = 0; t < NT; ++t) {
        int v = hist[t][tid];
        scratch[tid] = v;
        __syncthreads();
        for (int off = 1; off < 256; off <<= 1) {
            int x = (tid >= off) ? scratch[tid - off] : 0;
            __syncthreads();
            scratch[tid] += x;
            __syncthreads();
        }
        hist[t][tid] = scratch[tid] - v;           // exclusive prefix
        if (tid == 255) tot[t] = scratch[255];
        __syncthreads();
    }
    if (tid == 0) {
        int s = 0;
        for (int t = 0; t < NT; ++t) { tstart_s[t] = s; g_tstart[t] = s; s += tot[t]; }
        tstart_s[NT] = s; g_tstart[NT] = s;
    }
    __syncthreads();
    for (int t = 0; t < NT; ++t) hist[t][tid] += tstart_s[t];
    for (int i = 0; i < CH; ++i) {
        int ty = jt[s0 + i];
        g_perm[hist[ty][tid]++] = s0 + i;
    }
}

// ---------------- GEMM 1: h = selu(emb @ W1 + b1) --------------------------
__global__ __launch_bounds__(256) void gemm_h_kernel(
    const float* __restrict__ A, const float* __restrict__ B,
    const float* __restrict__ bias)
{
    __shared__ float As[8][128];
    __shared__ float Bs[8][128];
    int tid = threadIdx.x;
    int rb = blockIdx.y * 128;
    int cb = blockIdx.x * 128;
    int tx = tid & 15, ty = tid >> 4;
    float acc[8][8];
#pragma unroll
    for (int i = 0; i < 8; ++i)
#pragma unroll
        for (int j = 0; j < 8; ++j) acc[i][j] = 0.f;

    int am = tid >> 1, ak = (tid & 1) * 4;
    int bk = tid >> 5, bn = (tid & 31) * 4;

    for (int k0 = 0; k0 < Dd; k0 += 8) {
        float4 a4 = *(const float4*)(A + (size_t)(rb + am) * Dd + k0 + ak);
        float4 b4 = *(const float4*)(B + (size_t)(k0 + bk) * Dd + cb + bn);
        __syncthreads();
        As[ak + 0][am] = a4.x; As[ak + 1][am] = a4.y;
        As[ak + 2][am] = a4.z; As[ak + 3][am] = a4.w;
        *(float4*)&Bs[bk][bn] = b4;
        __syncthreads();
#pragma unroll
        for (int k = 0; k < 8; ++k) {
            float4 a0 = *(const float4*)&As[k][ty * 8];
            float4 a1 = *(const float4*)&As[k][ty * 8 + 4];
            float4 b0 = *(const float4*)&Bs[k][tx * 8];
            float4 b1 = *(const float4*)&Bs[k][tx * 8 + 4];
            float av[8] = {a0.x, a0.y, a0.z, a0.w, a1.x, a1.y, a1.z, a1.w};
            float bv[8] = {b0.x, b0.y, b0.z, b0.w, b1.x, b1.y, b1.z, b1.w};
#pragma unroll
            for (int i = 0; i < 8; ++i)
#pragma unroll
                for (int j = 0; j < 8; ++j) acc[i][j] = fmaf(av[i], bv[j], acc[i][j]);
        }
    }
    const float SC = 1.0507009873554805f, AL = 1.6732632423543772f;
#pragma unroll
    for (int i = 0; i < 8; ++i) {
        int row = rb + ty * 8 + i;
        float o[8];
#pragma unroll
        for (int j = 0; j < 8; ++j) {
            float v = acc[i][j] + bias[cb + tx * 8 + j];
            o[j] = (v > 0.f) ? SC * v : SC * AL * expm1f(v);
        }
        *(float4*)(g_h + (size_t)row * Dd + cb + tx * 8)     = make_float4(o[0], o[1], o[2], o[3]);
        *(float4*)(g_h + (size_t)row * Dd + cb + tx * 8 + 4) = make_float4(o[4], o[5], o[6], o[7]);
    }
}

// ---------------- squared row norms ----------------------------------------
__global__ void hnorm_kernel()
{
    int row = blockIdx.x * 8 + (threadIdx.x >> 5);
    int lane = threadIdx.x & 31;
    const float4* x = (const float4*)(g_h + (size_t)row * Dd);
    float s = 0.f;
#pragma unroll
    for (int i = 0; i < 2; ++i) {
        float4 v = x[lane + 32 * i];
        s += v.x * v.x + v.y * v.y + v.z * v.z + v.w * v.w;
    }
    s = wred_sum(s);
    if (lane == 0) g_hnorm[row] = s;
}
__global__ void pnorm_kernel(const float* __restrict__ P)
{
    int row = blockIdx.x * 8 + (threadIdx.x >> 5);
    int lane = threadIdx.x & 31;
    if (row >= 512) return;
    const float4* x = (const float4*)(P + (size_t)row * Dd);
    float s = 0.f;
#pragma unroll
    for (int i = 0; i < 2; ++i) {
        float4 v = x[lane + 32 * i];
        s += v.x * v.x + v.y * v.y + v.z * v.z + v.w * v.w;
    }
    s = wred_sum(s);
    if (lane == 0) g_pnorm[row] = s;
}

// ---- GEMM 2: M_sorted[i][j] = -max(0, |h_i|^2+|p_j|^2-2 h_i.p_j)/tau ------
__global__ __launch_bounds__(256) void gemm_M_kernel(const float* __restrict__ P)
{
    __shared__ float As[8][128];
    __shared__ float Bs[8][128];
    __shared__ int prow[128];
    int tid = threadIdx.x;
    int rb = blockIdx.y * 128;
    int cb = blockIdx.x * 128;
    int tx = tid & 15, ty = tid >> 4;
    if (tid < 128) prow[tid] = g_perm[rb + tid];
    __syncthreads();

    float acc[8][8];
#pragma unroll
    for (int i = 0; i < 8; ++i)
#pragma unroll
        for (int j = 0; j < 8; ++j) acc[i][j] = 0.f;

    int am = tid >> 1, ak = (tid & 1) * 4;   // A: h rows (gathered by perm)
    int bc = tid >> 1, bk = (tid & 1) * 4;   // B: prototype rows (K-major gather)
    int arow = prow[am];

    for (int k0 = 0; k0 < Dd; k0 += 8) {
        float4 a4 = *(const float4*)(g_h + (size_t)arow * Dd + k0 + ak);
        float4 b4 = *(const float4*)(P + (size_t)(cb + bc) * Dd + k0 + bk);
        __syncthreads();
        As[ak + 0][am] = a4.x; As[ak + 1][am] = a4.y;
        As[ak + 2][am] = a4.z; As[ak + 3][am] = a4.w;
        Bs[bk + 0][bc] = b4.x; Bs[bk + 1][bc] = b4.y;
        Bs[bk + 2][bc] = b4.z; Bs[bk + 3][bc] = b4.w;
        __syncthreads();
#pragma unroll
        for (int k = 0; k < 8; ++k) {
            float4 a0 = *(const float4*)&As[k][ty * 8];
            float4 a1 = *(const float4*)&As[k][ty * 8 + 4];
            float4 b0 = *(const float4*)&Bs[k][tx * 8];
            float4 b1 = *(const float4*)&Bs[k][tx * 8 + 4];
            float av[8] = {a0.x, a0.y, a0.z, a0.w, a1.x, a1.y, a1.z, a1.w};
            float bv[8] = {b0.x, b0.y, b0.z, b0.w, b1.x, b1.y, b1.z, b1.w};
#pragma unroll
            for (int i = 0; i < 8; ++i)
#pragma unroll
                for (int j = 0; j < 8; ++j) acc[i][j] = fmaf(av[i], bv[j], acc[i][j]);
        }
    }
#pragma unroll
    for (int i = 0; i < 8; ++i) {
        int srow = rb + ty * 8 + i;
        float hn = g_hnorm[prow[ty * 8 + i]];
#pragma unroll
        for (int j = 0; j < 8; ++j) {
            int col = cb + tx * 8 + j;
            if (col < KP) {
                float d2 = fmaxf(hn + g_pnorm[col] - 2.0f * acc[i][j], 0.0f);
                g_M[(size_t)srow * KP + col] = -d2 * INVTAU;
            }
        }
    }
}

// ---------------- persistent Sinkhorn + epilogue ---------------------------
__device__ __forceinline__ void grid_barrier(int epoch)
{
    int tid = threadIdx.x;
    __threadfence();
    __syncthreads();
    if (tid == 0) atomicExch(&g_flag[blockIdx.x], (unsigned)epoch);
    if (tid < NCTA) {
        volatile unsigned* vf = g_flag;
        while (vf[tid] < (unsigned)epoch) { }
    }
    __threadfence();
    __syncthreads();
}

__global__ __launch_bounds__(256, 1) void sinkhorn_kernel(
    float* __restrict__ out_logits, float* __restrict__ out_T)
{
    extern __shared__ float sm[];
    float* Ms   = sm;                        // ROWCAP*KP
    float* Vs   = sm + ROWCAP * KP;          // KP
    float* logu = Vs + KP + 4;               // ROWCAP
    __shared__ float vlast_s;

    int c = blockIdx.x, t = c >> 3, sub = c & 7;
    int tid = threadIdx.x, w = tid >> 5, l = tid & 31;
    int gs = g_tstart[t], ge = g_tstart[t + 1], len = ge - gs;
    int r0 = gs + (sub * len) / 8;
    int r1 = gs + ((sub + 1) * len) / 8;
    int rows = r1 - r0;
    if (rows > ROWCAP) rows = ROWCAP;

    for (int e = tid; e < rows * KP; e += 256)
        Ms[e] = g_M[(size_t)r0 * KP + e];
    __syncthreads();

    for (int it = 1; it <= ITERS + 1; ++it) {
        // -------- Phase A: combine previous column partials into V ---------
        if (it == 1) {
            for (int j = tid; j < KP; j += 256) Vs[j] = 0.f;
            if (tid == 0) vlast_s = 0.f;
        } else {
            int pp = (it - 1) & 1;
            for (int j = tid; j < KP; j += 256) {
                const float2* p = &g_cpart[pp][(t * KP + j) * 8];
                float2 v[8];
#pragma unroll
                for (int q = 0; q < 8; ++q) v[q] = __ldcg(p + q);
                float gm = DEV_NEG_INF;
#pragma unroll
                for (int q = 0; q < 8; ++q) gm = fmaxf(gm, v[q].x);
                float s = 0.f;
#pragma unroll
                for (int q = 0; q < 8; ++q)
                    if (v[q].y > 0.f) s += v[q].y * __expf(v[q].x - gm);
                Vs[j] = -(gm + logf(s));
            }
            if (tid < 32) {
                float2 up[5];
                float gm = DEV_NEG_INF;
#pragma unroll
                for (int q = 0; q < 5; ++q) {
                    int i = l + 32 * q;
                    up[q] = (i < NCTA) ? __ldcg(&g_upart[pp][i])
                                       : make_float2(DEV_NEG_INF, 0.f);
                    gm = fmaxf(gm, up[q].x);
                }
                gm = wred_max(gm);
                float s = 0.f;
#pragma unroll
                for (int q = 0; q < 5; ++q)
                    if (up[q].y > 0.f) s += up[q].y * __expf(up[q].x - gm);
                s = wred_sum(s);
                if (l == 0) vlast_s = logf(DUMMY_MASS) - (gm + logf(s));
            }
        }
        __syncthreads();
        float vlast = vlast_s;
        if (it == ITERS + 1) break;           // V now holds v after 30 iters

        // -------- Phase B: row LSE -> log_u --------------------------------
        for (int i = w; i < rows; i += 8) {
            const float* mr = Ms + i * KP;
            float m1 = vlast;                 // dummy column term (m=0)
            for (int j = l; j < KP; j += 32) m1 = fmaxf(m1, mr[j] + Vs[j]);
            m1 = wred_max(m1);
            float s = (l == 0) ? __expf(vlast - m1) : 0.f;
            for (int j = l; j < KP; j += 32) s += __expf(mr[j] + Vs[j] - m1);
            s = wred_sum(s);
            if (l == 0) logu[i] = -(m1 + logf(s));
        }
        __syncthreads();

        // -------- Phase C: column (max,sumexp) partials --------------------
        int pw = it & 1;
        for (int j = tid; j < KP; j += 256) {
            float m1 = DEV_NEG_INF;
            for (int i = 0; i < rows; ++i) m1 = fmaxf(m1, Ms[i * KP + j] + logu[i]);
            float s = 0.f;
            for (int i = 0; i < rows; ++i) s += __expf(Ms[i * KP + j] + logu[i] - m1);
            __stcg(&g_cpart[pw][(t * KP + j) * 8 + sub], make_float2(m1, s));
        }
        if (tid < 32) {
            float m1 = DEV_NEG_INF;
            for (int i = l; i < rows; i += 32) m1 = fmaxf(m1, logu[i]);
            m1 = wred_max(m1);
            float s = 0.f;
            for (int i = l; i < rows; i += 32) s += __expf(logu[i] - m1);
            s = wred_sum(s);
            if (l == 0) __stcg(&g_upart[pw][c], make_float2(m1, s));
        }
        grid_barrier(it);
    }

    // -------- Epilogue: T nonzeros + logits --------------------------------
    for (int i = w; i < rows; i += 8) {
        int n = g_perm[r0 + i];
        float lu = logu[i];
        const float* mr = Ms + i * KP;
        float* Trow = out_T + (size_t)n * NSLOT + t;
        float* Lrow = out_logits + (size_t)n * KP;
        for (int j = l; j < KP; j += 32) {
            float val = __expf(mr[j] + lu + Vs[j]);
            Trow[j * NT] = val;
            Lrow[j] = logf(val + 1e-8f);
        }
    }
}

// ---------------- launch ----------------------------------------------------
extern "C" void kernel_launch(void* const* d_in, const int* in_sizes, int n_in,
                              void* d_out, int out_size)
{
    const float* emb   = (const float*)d_in[0];
    const float* W1    = (const float*)d_in[1];
    const float* b1    = (const float*)d_in[2];
    const float* proto = (const float*)d_in[3];
    const int*   jt    = (const int*)d_in[4];
    (void)in_sizes; (void)n_in; (void)out_size;   // k fixed at 300

    float* logits = (float*)d_out;
    float* T      = logits + (size_t)Nn * KP;

    size_t smem = (size_t)(ROWCAP * KP + KP + 4 + ROWCAP + 8) * sizeof(float);
    cudaFuncSetAttribute(sinkhorn_kernel,
                         cudaFuncAttributeMaxDynamicSharedMemorySize, (int)smem);

    sort_kernel<<<1, 256>>>(jt);
    gemm_h_kernel<<<dim3(Dd / 128, Nn / 128), 256>>>(emb, W1, b1);
    hnorm_kernel<<<Nn / 8, 256>>>();
    pnorm_kernel<<<64, 256>>>(proto);
    gemm_M_kernel<<<dim3(3, Nn / 128), 256>>>(proto);
    cudaMemsetAsync(T, 0, (size_t)Nn * NSLOT * sizeof(float));
    sinkhorn_kernel<<<NCTA, 256, smem>>>(logits, T);
}